// round 4
// baseline (speedup 1.0000x reference)
#include <cuda_runtime.h>
#include <math.h>

// ---------------------------------------------------------------------------
// FCOS head, fp32. Implicit-GEMM conv3x3 (SAME pad), GroupNorm(32)+ReLU,
// heads write directly into the permuted [pixel][85] output layout.
// ---------------------------------------------------------------------------

#define KTOT 2304   // IC(256) * 9

// Scratch (max level: 256 ch * 80*80)
__device__ float g_raw[256 * 6400];
__device__ float g_act[256 * 6400];
__device__ float g_stats[64];   // 32 groups * {mean, rstd}

// ---------------------------------------------------------------------------
// Implicit-GEMM conv: out = W[OC,2304] x im2col[2304,HW] + bias
// Block tile 64(OC) x 64(pixels) x 16(K), 256 threads, 4x4 microtile.
// MODE 0: tower  -> out[oc*HW + p] = v
// MODE 1: head   -> out[p*85 + ocOff + oc] = v              (score / iou)
// MODE 2: pred   -> out[p*85 + ocOff + oc] = relu(v*scale)*strideMul
// ---------------------------------------------------------------------------
template <int MODE>
__global__ __launch_bounds__(256) void conv_kernel(
    const float* __restrict__ in,      // [256][H][W]
    const float* __restrict__ w,       // [OC][2304]
    const float* __restrict__ bias,    // [OC]
    float* __restrict__ out,
    int OC, int H, int W,
    int ocOff, const float* __restrict__ scalePtr, float strideMul)
{
    const int HW = H * W;
    __shared__ float As[64][17];   // [oc][k]
    __shared__ float Bs[16][64];   // [k][pixel]

    const int tid = threadIdx.x;
    const int tx = tid & 15;       // pixel quad
    const int ty = tid >> 4;       // oc quad
    const int pBase  = blockIdx.x * 64;
    const int ocBase = blockIdx.y * 64;

    // Precompute per-slot constants (slot index fixed across K loop).
    int bk[4], bp[4], bh[4], bw[4];
    bool bvld[4];
    int aoc[4], ak[4];
#pragma unroll
    for (int i = 0; i < 4; i++) {
        int idx = tid + i * 256;          // 0..1023
        // B slot: k = idx/64, p = idx%64  (consecutive threads -> consecutive p)
        bk[i] = idx >> 6;
        int p = idx & 63;
        bp[i] = p;
        int pp = pBase + p;
        bvld[i] = (pp < HW);
        int h = bvld[i] ? (pp / W) : 0;
        bh[i] = h;
        bw[i] = bvld[i] ? (pp - h * W) : 0;
        // A slot: oc = idx/16, k = idx%16 (consecutive threads -> consecutive k)
        aoc[i] = idx >> 4;
        ak[i]  = idx & 15;
    }

    float acc[4][4] = {};

    for (int k0 = 0; k0 < KTOT; k0 += 16) {
        // Load weight tile
#pragma unroll
        for (int i = 0; i < 4; i++) {
            int oc = ocBase + aoc[i];
            As[aoc[i]][ak[i]] =
                (oc < OC) ? w[(size_t)oc * KTOT + k0 + ak[i]] : 0.f;
        }
        // Load im2col tile
#pragma unroll
        for (int i = 0; i < 4; i++) {
            int kk = k0 + bk[i];
            int ic = kk / 9;
            int rs = kk - ic * 9;
            int r  = rs / 3;
            int s  = rs - r * 3;
            int row = bh[i] + r - 1;
            int col = bw[i] + s - 1;
            float v = 0.f;
            if (bvld[i] && (unsigned)row < (unsigned)H && (unsigned)col < (unsigned)W)
                v = in[(size_t)ic * HW + row * W + col];
            Bs[bk[i]][bp[i]] = v;
        }
        __syncthreads();

#pragma unroll
        for (int k = 0; k < 16; k++) {
            float a0 = As[ty * 4 + 0][k];
            float a1 = As[ty * 4 + 1][k];
            float a2 = As[ty * 4 + 2][k];
            float a3 = As[ty * 4 + 3][k];
            float b0 = Bs[k][tx * 4 + 0];
            float b1 = Bs[k][tx * 4 + 1];
            float b2 = Bs[k][tx * 4 + 2];
            float b3 = Bs[k][tx * 4 + 3];
            acc[0][0] = fmaf(a0, b0, acc[0][0]);
            acc[0][1] = fmaf(a0, b1, acc[0][1]);
            acc[0][2] = fmaf(a0, b2, acc[0][2]);
            acc[0][3] = fmaf(a0, b3, acc[0][3]);
            acc[1][0] = fmaf(a1, b0, acc[1][0]);
            acc[1][1] = fmaf(a1, b1, acc[1][1]);
            acc[1][2] = fmaf(a1, b2, acc[1][2]);
            acc[1][3] = fmaf(a1, b3, acc[1][3]);
            acc[2][0] = fmaf(a2, b0, acc[2][0]);
            acc[2][1] = fmaf(a2, b1, acc[2][1]);
            acc[2][2] = fmaf(a2, b2, acc[2][2]);
            acc[2][3] = fmaf(a2, b3, acc[2][3]);
            acc[3][0] = fmaf(a3, b0, acc[3][0]);
            acc[3][1] = fmaf(a3, b1, acc[3][1]);
            acc[3][2] = fmaf(a3, b2, acc[3][2]);
            acc[3][3] = fmaf(a3, b3, acc[3][3]);
        }
        __syncthreads();
    }

    float sc = 1.f;
    if (MODE == 2) sc = __ldg(scalePtr);

#pragma unroll
    for (int i = 0; i < 4; i++) {
        int oc = ocBase + ty * 4 + i;
        if (oc >= OC) continue;
        float bb = bias[oc];
#pragma unroll
        for (int j = 0; j < 4; j++) {
            int p = pBase + tx * 4 + j;
            if (p >= HW) continue;
            float v = acc[i][j] + bb;
            if (MODE == 0) {
                out[(size_t)oc * HW + p] = v;
            } else if (MODE == 1) {
                out[(size_t)p * 85 + ocOff + oc] = v;
            } else {
                v = fmaxf(v * sc, 0.f) * strideMul;
                out[(size_t)p * 85 + ocOff + oc] = v;
            }
        }
    }
}

// ---------------------------------------------------------------------------
// GroupNorm stats: one block per group (32 groups, 8 channels each).
// ---------------------------------------------------------------------------
__global__ __launch_bounds__(256) void gn_stats_kernel(
    const float* __restrict__ x, float* __restrict__ stats, int HW)
{
    const int g = blockIdx.x;
    const float* xp = x + (size_t)g * 8 * HW;
    const int n = 8 * HW;
    float s = 0.f, ss = 0.f;
    for (int i = threadIdx.x; i < n; i += 256) {
        float v = xp[i];
        s += v;
        ss = fmaf(v, v, ss);
    }
    __shared__ float sh0[256], sh1[256];
    sh0[threadIdx.x] = s;
    sh1[threadIdx.x] = ss;
    __syncthreads();
    for (int o = 128; o > 0; o >>= 1) {
        if (threadIdx.x < o) {
            sh0[threadIdx.x] += sh0[threadIdx.x + o];
            sh1[threadIdx.x] += sh1[threadIdx.x + o];
        }
        __syncthreads();
    }
    if (threadIdx.x == 0) {
        float inv_n = 1.f / (float)n;
        float mean = sh0[0] * inv_n;
        float var = sh1[0] * inv_n - mean * mean;
        stats[g * 2 + 0] = mean;
        stats[g * 2 + 1] = rsqrtf(fmaxf(var, 0.f) + 1e-5f);
    }
}

// ---------------------------------------------------------------------------
// Apply GN + ReLU. grid = (ceil(HW/256), 256 channels)
// ---------------------------------------------------------------------------
__global__ __launch_bounds__(256) void gn_apply_kernel(
    const float* __restrict__ x, const float* __restrict__ stats,
    const float* __restrict__ gamma, const float* __restrict__ beta,
    float* __restrict__ y, int HW)
{
    const int c = blockIdx.y;
    const int g = c >> 3;
    float mean = stats[g * 2 + 0];
    float rstd = stats[g * 2 + 1];
    float ga = gamma[c] * rstd;
    float be = fmaf(-mean, ga, beta[c]);   // beta - mean*rstd*gamma
    int p = blockIdx.x * 256 + threadIdx.x;
    if (p < HW) {
        float v = x[(size_t)c * HW + p];
        y[(size_t)c * HW + p] = fmaxf(fmaf(v, ga, be), 0.f);
    }
}

// ---------------------------------------------------------------------------
// Host driver
// ---------------------------------------------------------------------------
static void run_tower(const float* feat, const float* w, const float* b,
                      const float* gw, const float* gb,
                      float* raw, float* act, float* stats,
                      int H, int W)
{
    const int HW = H * W;
    dim3 cgrid((HW + 63) / 64, 4);                  // 256 OC / 64
    dim3 agrid((HW + 255) / 256, 256);
    const float* cur = feat;
    for (int i = 0; i < 4; i++) {
        conv_kernel<0><<<cgrid, 256>>>(cur, w + (size_t)i * 256 * KTOT,
                                       b + i * 256, raw, 256, H, W,
                                       0, nullptr, 0.f);
        gn_stats_kernel<<<32, 256>>>(raw, stats, HW);
        gn_apply_kernel<<<agrid, 256>>>(raw, stats, gw + i * 256, gb + i * 256,
                                        act, HW);
        cur = act;
    }
}

extern "C" void kernel_launch(void* const* d_in, const int* in_sizes, int n_in,
                              void* d_out, int out_size)
{
    const float* feats[5] = {
        (const float*)d_in[0], (const float*)d_in[1], (const float*)d_in[2],
        (const float*)d_in[3], (const float*)d_in[4]
    };
    const float* cls_w    = (const float*)d_in[5];
    const float* cls_b    = (const float*)d_in[6];
    const float* cls_gn_w = (const float*)d_in[7];
    const float* cls_gn_b = (const float*)d_in[8];
    const float* box_w    = (const float*)d_in[9];
    const float* box_b    = (const float*)d_in[10];
    const float* box_gn_w = (const float*)d_in[11];
    const float* box_gn_b = (const float*)d_in[12];
    const float* score_w  = (const float*)d_in[13];
    const float* score_b  = (const float*)d_in[14];
    const float* pred_w   = (const float*)d_in[15];
    const float* pred_b   = (const float*)d_in[16];
    const float* iou_w    = (const float*)d_in[17];
    const float* iou_b    = (const float*)d_in[18];
    const float* scales   = (const float*)d_in[19];

    float* raw;   cudaGetSymbolAddress((void**)&raw,   g_raw);
    float* act;   cudaGetSymbolAddress((void**)&act,   g_act);
    float* stats; cudaGetSymbolAddress((void**)&stats, g_stats);

    float* out = (float*)d_out;
    const int Hs[5] = {80, 40, 20, 10, 5};
    const float strideF[5] = {8.f, 16.f, 32.f, 64.f, 128.f};

    int pixOff = 0;
    for (int l = 0; l < 5; l++) {
        const int H = Hs[l], W = Hs[l], HW = H * W;
        float* outBase = out + (size_t)pixOff * 85;

        // ---- cls tower -> act, then score conv (80 ch, cols 0..79) ----
        run_tower(feats[l], cls_w, cls_b, cls_gn_w, cls_gn_b,
                  raw, act, stats, H, W);
        {
            dim3 g((HW + 63) / 64, 2);   // 80 OC -> 2 blocks of 64
            conv_kernel<1><<<g, 256>>>(act, score_w, score_b, outBase,
                                       80, H, W, 0, nullptr, 0.f);
        }

        // ---- box tower -> act, then pred (4 ch, cols 80..83) + iou (col 84)
        run_tower(feats[l], box_w, box_b, box_gn_w, box_gn_b,
                  raw, act, stats, H, W);
        {
            dim3 g((HW + 63) / 64, 1);
            conv_kernel<2><<<g, 256>>>(act, pred_w, pred_b, outBase,
                                       4, H, W, 80, scales + l, strideF[l]);
            conv_kernel<1><<<g, 256>>>(act, iou_w, iou_b, outBase,
                                       1, H, W, 84, nullptr, 0.f);
        }
        pixOff += HW;
    }
}

// round 5
// speedup vs baseline: 2.7249x; 2.7249x over previous
#include <cuda_runtime.h>
#include <math.h>

// ---------------------------------------------------------------------------
// FCOS head, fp32, fully batched across towers and FPN levels.
//   4x [ conv3x3(256->256) -> GN(32) -> ReLU ]  (cls + box towers, 5 levels,
//   all in ONE launch per step), then batched head convs writing directly
//   into the permuted [pixel][85] output.
// ---------------------------------------------------------------------------

#define KTOT 2304          // 256 IC * 9
#define CH   256
#define NPIX 8525          // 80^2+40^2+20^2+10^2+5^2

__device__ float g_raw[2][CH * NPIX];     // per-tower conv output (pre-GN)
__device__ float g_act[2][CH * NPIX];     // per-tower activation (post GN+ReLU)
__device__ float g_stats[2 * 5 * 32 * 2]; // [tower][level][group]{mean,rstd}

__constant__ int   c_Hc[5]      = {80, 40, 20, 10, 5};
__constant__ int   c_HWc[5]     = {6400, 1600, 400, 100, 25};
__constant__ int   c_cumHW[5]   = {0, 6400, 8000, 8400, 8500};
__constant__ int   c_pbCum[5]   = {100, 125, 132, 134, 135}; // 64-px blocks, upper cum
__constant__ int   c_apCum[5]   = {25, 32, 34, 35, 36};      // 256-px blocks, upper cum
__constant__ float c_strideF[5] = {8.f, 16.f, 32.f, 64.f, 128.f};

// ---------------------------------------------------------------------------
// 64(oc) x 64(pix) x 16(k) implicit-GEMM tile, 256 threads, 4x4 microtile.
// As stored [k][oc] (padded) so the inner loop is 2x LDS.128 + 16 FFMA per k.
// Weight rows < split come from w1, >= split from w2 (reindexed).
// ---------------------------------------------------------------------------
__device__ __forceinline__ void gemm64x64(
    const float* __restrict__ in, int H, int W, int HW,
    int pBase, int ocBase, int OC, int split,
    const float* __restrict__ w1, const float* __restrict__ w2,
    float acc[4][4])
{
    __shared__ float As[16][68];   // [k][oc] (+4 pad)
    __shared__ float Bs[16][64];   // [k][pixel]

    const int tid = threadIdx.x;

    int ak[4], aoc[4], bk[4], bp[4], bh[4], bw[4], ic[4], rs[4];
    bool bvld[4];
    const float* wrow[4];
#pragma unroll
    for (int i = 0; i < 4; i++) {
        int idx = tid + i * 256;            // 0..1023
        ak[i]  = idx & 15;                  // consecutive tids -> consecutive k (coalesced gmem)
        aoc[i] = idx >> 4;
        int oc = ocBase + aoc[i];
        wrow[i] = (oc < OC)
            ? ((oc < split) ? w1 + (size_t)oc * KTOT
                            : w2 + (size_t)(oc - split) * KTOT)
            : (const float*)0;
        bk[i] = idx >> 6;                   // 0..15
        bp[i] = idx & 63;
        int pp = pBase + bp[i];
        bvld[i] = (pp < HW);
        int h = bvld[i] ? pp / W : 0;
        bh[i] = h;
        bw[i] = bvld[i] ? pp - h * W : 0;
        ic[i] = bk[i] / 9;                  // 0 or 1
        rs[i] = bk[i] - ic[i] * 9;
    }

    for (int k0 = 0; k0 < KTOT; k0 += 16) {
#pragma unroll
        for (int i = 0; i < 4; i++)
            As[ak[i]][aoc[i]] = wrow[i] ? wrow[i][k0 + ak[i]] : 0.f;
#pragma unroll
        for (int i = 0; i < 4; i++) {
            int r = rs[i] / 3;
            int s = rs[i] - r * 3;
            int row = bh[i] + r - 1;
            int col = bw[i] + s - 1;
            float v = 0.f;
            if (bvld[i] && (unsigned)row < (unsigned)H && (unsigned)col < (unsigned)W)
                v = in[(size_t)ic[i] * HW + row * W + col];
            Bs[bk[i]][bp[i]] = v;
            // advance k by 16 for next tile: ic*9 + rs tracks it
            rs[i] += 16;
            if (rs[i] >= 9) { rs[i] -= 9; ic[i]++; }
            if (rs[i] >= 9) { rs[i] -= 9; ic[i]++; }
        }
        __syncthreads();

        const int tx = tid & 15, ty = tid >> 4;
#pragma unroll
        for (int k = 0; k < 16; k++) {
            float4 a = *(const float4*)&As[k][ty * 4];
            float4 b = *(const float4*)&Bs[k][tx * 4];
            acc[0][0] = fmaf(a.x, b.x, acc[0][0]);
            acc[0][1] = fmaf(a.x, b.y, acc[0][1]);
            acc[0][2] = fmaf(a.x, b.z, acc[0][2]);
            acc[0][3] = fmaf(a.x, b.w, acc[0][3]);
            acc[1][0] = fmaf(a.y, b.x, acc[1][0]);
            acc[1][1] = fmaf(a.y, b.y, acc[1][1]);
            acc[1][2] = fmaf(a.y, b.z, acc[1][2]);
            acc[1][3] = fmaf(a.y, b.w, acc[1][3]);
            acc[2][0] = fmaf(a.z, b.x, acc[2][0]);
            acc[2][1] = fmaf(a.z, b.y, acc[2][1]);
            acc[2][2] = fmaf(a.z, b.z, acc[2][2]);
            acc[2][3] = fmaf(a.z, b.w, acc[2][3]);
            acc[3][0] = fmaf(a.w, b.x, acc[3][0]);
            acc[3][1] = fmaf(a.w, b.y, acc[3][1]);
            acc[3][2] = fmaf(a.w, b.z, acc[3][2]);
            acc[3][3] = fmaf(a.w, b.w, acc[3][3]);
        }
        __syncthreads();
    }
}

__device__ __forceinline__ int decode_level(int bx, const int* cum)
{
    int l = 0;
    if (bx >= cum[0]) l = 1;
    if (bx >= cum[1]) l = 2;
    if (bx >= cum[2]) l = 3;
    if (bx >= cum[3]) l = 4;
    return l;
}

// ---------------------------------------------------------------------------
// Tower conv step: grid (135 pixel-blocks, 4 oc-blocks, 2 towers)
// ---------------------------------------------------------------------------
__global__ __launch_bounds__(256) void tower_conv(
    const float* __restrict__ f0, const float* __restrict__ f1,
    const float* __restrict__ f2, const float* __restrict__ f3,
    const float* __restrict__ f4,
    const float* __restrict__ wCls, const float* __restrict__ wBox,
    const float* __restrict__ bCls, const float* __restrict__ bBox,
    int step)
{
    const int bx = blockIdx.x;
    const int l = decode_level(bx, c_pbCum);
    const int pixBase = (bx - (l ? c_pbCum[l - 1] : 0)) * 64;
    const int H = c_Hc[l], W = H, HW = c_HWc[l];
    const int t = blockIdx.z;
    const int ocBase = blockIdx.y * 64;

    const float* in;
    if (step == 0)
        in = (l == 0) ? f0 : (l == 1) ? f1 : (l == 2) ? f2 : (l == 3) ? f3 : f4;
    else
        in = &g_act[t][(size_t)CH * c_cumHW[l]];

    const float* w = (t ? wBox : wCls) + (size_t)step * CH * KTOT;
    const float* b = (t ? bBox : bCls) + step * CH;

    float acc[4][4] = {};
    gemm64x64(in, H, W, HW, pixBase, ocBase, CH, CH, w, w, acc);

    float* out = &g_raw[t][(size_t)CH * c_cumHW[l]];
    const int tx = threadIdx.x & 15, ty = threadIdx.x >> 4;
#pragma unroll
    for (int i = 0; i < 4; i++) {
        int oc = ocBase + ty * 4 + i;
        float bb = b[oc];
#pragma unroll
        for (int j = 0; j < 4; j++) {
            int p = pixBase + tx * 4 + j;
            if (p < HW) out[(size_t)oc * HW + p] = acc[i][j] + bb;
        }
    }
}

// ---------------------------------------------------------------------------
// Head convs: grid (135, ceil(OC/64)). predMode: oc<4 -> relu(v*scale)*stride,
// oc==4 -> iou passthrough. Writes [pixel][85] layout directly.
// ---------------------------------------------------------------------------
__global__ __launch_bounds__(256) void head_conv(
    const float* __restrict__ w1, const float* __restrict__ w2,
    const float* __restrict__ b1, const float* __restrict__ b2,
    int split, int OC, int tower, int ocOut, int predMode,
    const float* __restrict__ scales,
    float* __restrict__ out)
{
    const int bx = blockIdx.x;
    const int l = decode_level(bx, c_pbCum);
    const int pixBase = (bx - (l ? c_pbCum[l - 1] : 0)) * 64;
    const int H = c_Hc[l], W = H, HW = c_HWc[l];
    const int ocBase = blockIdx.y * 64;

    const float* in = &g_act[tower][(size_t)CH * c_cumHW[l]];

    float acc[4][4] = {};
    gemm64x64(in, H, W, HW, pixBase, ocBase, OC, split, w1, w2, acc);

    float sc = 1.f, sm = 1.f;
    if (predMode) { sc = __ldg(&scales[l]); sm = c_strideF[l]; }

    const int tx = threadIdx.x & 15, ty = threadIdx.x >> 4;
#pragma unroll
    for (int i = 0; i < 4; i++) {
        int oc = ocBase + ty * 4 + i;
        if (oc >= OC) continue;
        float bb = (oc < split) ? b1[oc] : b2[oc - split];
#pragma unroll
        for (int j = 0; j < 4; j++) {
            int p = pixBase + tx * 4 + j;
            if (p >= HW) continue;
            float v = acc[i][j] + bb;
            if (predMode && oc < 4) v = fmaxf(v * sc, 0.f) * sm;
            out[(size_t)(c_cumHW[l] + p) * 85 + ocOut + oc] = v;
        }
    }
}

// ---------------------------------------------------------------------------
// GroupNorm stats: grid (32 groups, 5 levels, 2 towers)
// ---------------------------------------------------------------------------
__global__ __launch_bounds__(256) void gn_stats()
{
    const int g = blockIdx.x, l = blockIdx.y, t = blockIdx.z;
    const int HW = c_HWc[l];
    const float4* x4 = (const float4*)&g_raw[t][(size_t)CH * c_cumHW[l] +
                                               (size_t)g * 8 * HW];
    const int n = 8 * HW;
    const int n4 = n >> 2;

    float s = 0.f, ss = 0.f;
    for (int i = threadIdx.x; i < n4; i += 256) {
        float4 v = x4[i];
        s += (v.x + v.y) + (v.z + v.w);
        ss = fmaf(v.x, v.x, ss);
        ss = fmaf(v.y, v.y, ss);
        ss = fmaf(v.z, v.z, ss);
        ss = fmaf(v.w, v.w, ss);
    }
    __shared__ float sh0[256], sh1[256];
    sh0[threadIdx.x] = s;
    sh1[threadIdx.x] = ss;
    __syncthreads();
    for (int o = 128; o > 0; o >>= 1) {
        if (threadIdx.x < o) {
            sh0[threadIdx.x] += sh0[threadIdx.x + o];
            sh1[threadIdx.x] += sh1[threadIdx.x + o];
        }
        __syncthreads();
    }
    if (threadIdx.x == 0) {
        float inv_n = 1.f / (float)n;
        float mean = sh0[0] * inv_n;
        float var = sh1[0] * inv_n - mean * mean;
        int sidx = ((t * 5 + l) * 32 + g) * 2;
        g_stats[sidx]     = mean;
        g_stats[sidx + 1] = rsqrtf(fmaxf(var, 0.f) + 1e-5f);
    }
}

// ---------------------------------------------------------------------------
// GN apply + ReLU: grid (36 pixel-blocks, 256 channels, 2 towers)
// ---------------------------------------------------------------------------
__global__ __launch_bounds__(256) void gn_apply(
    const float* __restrict__ gwCls, const float* __restrict__ gbCls,
    const float* __restrict__ gwBox, const float* __restrict__ gbBox,
    int step)
{
    const int bx = blockIdx.x;
    const int l = decode_level(bx, c_apCum);
    const int HW = c_HWc[l];
    const int p = (bx - (l ? c_apCum[l - 1] : 0)) * 256 + threadIdx.x;
    if (p >= HW) return;

    const int c = blockIdx.y, t = blockIdx.z;
    const float* gw = (t ? gwBox : gwCls) + step * CH;
    const float* gb = (t ? gbBox : gbCls) + step * CH;

    const int sidx = ((t * 5 + l) * 32 + (c >> 3)) * 2;
    float mean = g_stats[sidx];
    float rstd = g_stats[sidx + 1];
    float ga = gw[c] * rstd;
    float be = fmaf(-mean, ga, gb[c]);

    size_t base = (size_t)CH * c_cumHW[l] + (size_t)c * HW;
    float v = g_raw[t][base + p];
    g_act[t][base + p] = fmaxf(fmaf(v, ga, be), 0.f);
}

// ---------------------------------------------------------------------------
// Host driver: 14 launches total
// ---------------------------------------------------------------------------
extern "C" void kernel_launch(void* const* d_in, const int* in_sizes, int n_in,
                              void* d_out, int out_size)
{
    const float* f0 = (const float*)d_in[0];
    const float* f1 = (const float*)d_in[1];
    const float* f2 = (const float*)d_in[2];
    const float* f3 = (const float*)d_in[3];
    const float* f4 = (const float*)d_in[4];
    const float* cls_w    = (const float*)d_in[5];
    const float* cls_b    = (const float*)d_in[6];
    const float* cls_gn_w = (const float*)d_in[7];
    const float* cls_gn_b = (const float*)d_in[8];
    const float* box_w    = (const float*)d_in[9];
    const float* box_b    = (const float*)d_in[10];
    const float* box_gn_w = (const float*)d_in[11];
    const float* box_gn_b = (const float*)d_in[12];
    const float* score_w  = (const float*)d_in[13];
    const float* score_b  = (const float*)d_in[14];
    const float* pred_w   = (const float*)d_in[15];
    const float* pred_b   = (const float*)d_in[16];
    const float* iou_w    = (const float*)d_in[17];
    const float* iou_b    = (const float*)d_in[18];
    const float* scales   = (const float*)d_in[19];
    float* out = (float*)d_out;

    for (int step = 0; step < 4; step++) {
        tower_conv<<<dim3(135, 4, 2), 256>>>(f0, f1, f2, f3, f4,
                                             cls_w, box_w, cls_b, box_b, step);
        gn_stats<<<dim3(32, 5, 2), 256>>>();
        gn_apply<<<dim3(36, 256, 2), 256>>>(cls_gn_w, cls_gn_b,
                                            box_gn_w, box_gn_b, step);
    }

    // score: 80 channels from cls tower -> cols 0..79
    head_conv<<<dim3(135, 2), 256>>>(score_w, score_w, score_b, score_b,
                                     80, 80, 0, 0, 0, scales, out);
    // pred (4ch, scale+relu+stride) + iou (1ch) from box tower -> cols 80..84
    head_conv<<<dim3(135, 1), 256>>>(pred_w, iou_w, pred_b, iou_b,
                                     4, 5, 1, 80, 1, scales, out);
}